// round 7
// baseline (speedup 1.0000x reference)
#include <cuda_runtime.h>
#include <cuda_bf16.h>

#define S 128
#define NROWS 4096
#define RPB 4                 // rows per block (one warp per row)
#define NBLK (NROWS / RPB)    // 1024 blocks

__device__ float4 g_part[NBLK];
__device__ unsigned int g_ticket;   // zero at load; reset by last block each run

__device__ __forceinline__ void fma2(unsigned long long& c,
                                     unsigned long long a,
                                     unsigned long long b) {
    asm("fma.rn.f32x2 %0, %1, %2, %0;" : "+l"(c) : "l"(a), "l"(b));
}
__device__ __forceinline__ float2 unpk(unsigned long long v) {
    float2 r;
    asm("mov.b64 {%0, %1}, %2;" : "=f"(r.x), "=f"(r.y) : "l"(v));
    return r;
}

__global__ void __launch_bounds__(128) loss3_fused(const float* __restrict__ outp,
                                                   const float* __restrict__ trut,
                                                   float* __restrict__ out) {
    __shared__ float so2[RPB][2 * S];   // output row, duplicated (wrap-free)
    __shared__ float so1[RPB][2 * S];   // so1[i] = o[(i+1) mod 128], duplicated
    __shared__ float st[RPB][S];        // truth row
    __shared__ float4 wres[RPB];
    __shared__ unsigned int sLast;

    const int tid = threadIdx.x;
    const int w = tid >> 5;     // warp = row within block
    const int l = tid & 31;     // lane
    const int row = blockIdx.x * RPB + w;

    // ---- load row (coalesced float4), mirror into smem ----
    float4 o4 = *(const float4*)(outp + row * S + 4 * l);
    float4 t4 = *(const float4*)(trut + row * S + 4 * l);
    *(float4*)&so2[w][4 * l]     = o4;
    *(float4*)&so2[w][S + 4 * l] = o4;
    *(float4*)&st[w][4 * l]      = t4;
    // shifted copy: so1[4l..4l+3] = o[4l+1..4l+4]
    float nx = __shfl_sync(0xffffffffu, o4.x, (l + 1) & 31);
    float4 s1 = make_float4(o4.y, o4.z, o4.w, nx);
    *(float4*)&so1[w][4 * l]     = s1;
    *(float4*)&so1[w][S + 4 * l] = s1;
    __syncwarp();

    // ---- row MSE (direct), max(output), max(truth): warp shuffles ----
    float d0 = o4.x - t4.x, d1 = o4.y - t4.y, d2 = o4.z - t4.z, d3 = o4.w - t4.w;
    float ms = d0 * d0 + d1 * d1 + d2 * d2 + d3 * d3;
    float mo = fmaxf(fmaxf(o4.x, o4.y), fmaxf(o4.z, o4.w));
    float mt = fmaxf(fmaxf(t4.x, t4.y), fmaxf(t4.z, t4.w));
#pragma unroll
    for (int s = 16; s > 0; s >>= 1) {
        ms += __shfl_xor_sync(0xffffffffu, ms, s);
        mo = fmaxf(mo, __shfl_xor_sync(0xffffffffu, mo, s));
        mt = fmaxf(mt, __shfl_xor_sync(0xffffffffu, mt, s));
    }

    // ---- circular correlation, fully packed f32x2 ----
    // acc[k] = sum_j o[(j-(4l+k))&127] * t[j];  o[(j-s)&127] = so2[j-s+S]
    // b0 = S-4l-4.  Relative offsets per J-step (+m means so2[b0+J+m]):
    //   k=0: {+4,+5}{t01} {+6,+7}{t23} = U.x,U.y      (U  = so2[b0+J+4..+7])
    //   k=1: {+3,+4}{t01} {+5,+6}{t23} = Vp.y,V.x     (V  = so1[b0+J+4..+7])
    //   k=2: {+2,+3}{t01} {+4,+5}{t23} = Up.y,U.x     (Up = U from J-4)
    //   k=3: {+1,+2}{t01} {+3,+4}{t23} = Vp.x,Vp.y    (Vp = V from J-4)
    const float* ob  = &so2[w][S - 4 * l - 4];
    const float* ob1 = &so1[w][S - 4 * l - 4];
    const float* tb  = &st[w][0];
    unsigned long long A0 = 0ull, A1 = 0ull, A2 = 0ull, A3 = 0ull;
    ulonglong2 Up = *(const ulonglong2*)(ob);    // so2[b0..b0+3]
    ulonglong2 Vp = *(const ulonglong2*)(ob1);   // so2[b0+1..b0+4]
#pragma unroll
    for (int J = 0; J < S; J += 4) {
        ulonglong2 U = *(const ulonglong2*)(ob + J + 4);
        ulonglong2 V = *(const ulonglong2*)(ob1 + J + 4);
        ulonglong2 T = *(const ulonglong2*)(tb + J);   // uniform -> broadcast
        fma2(A0, U.x,  T.x);
        fma2(A0, U.y,  T.y);
        fma2(A1, Vp.y, T.x);
        fma2(A1, V.x,  T.y);
        fma2(A2, Up.y, T.x);
        fma2(A2, U.x,  T.y);
        fma2(A3, Vp.x, T.x);
        fma2(A3, Vp.y, T.y);
        Up = U;
        Vp = V;
    }
    float2 p0 = unpk(A0), p1 = unpk(A1), p2 = unpk(A2), p3 = unpk(A3);
    float acc0 = p0.x + p0.y;
    float acc1 = p1.x + p1.y;
    float acc2 = p2.x + p2.y;
    float acc3 = p3.x + p3.y;

    // ---- argmax corr == argmin shiftDiff; tie-break -> smaller shift ----
    float bc = acc0; int bs = 4 * l;
    if (acc1 > bc) { bc = acc1; bs = 4 * l + 1; }
    if (acc2 > bc) { bc = acc2; bs = 4 * l + 2; }
    if (acc3 > bc) { bc = acc3; bs = 4 * l + 3; }
#pragma unroll
    for (int s = 16; s > 0; s >>= 1) {
        float oc = __shfl_xor_sync(0xffffffffu, bc, s);
        int   os = __shfl_xor_sync(0xffffffffu, bs, s);
        if (oc > bc || (oc == bc && os < bs)) { bc = oc; bs = os; }
    }
    const int b = bs;
    const float scale = mt / mo;   // max(rolled) == max(output): roll is a permutation

    // ---- detail loss: g = cgrad(rolled*scale - truth), cgrad linear ----
    // d[i] = o[(i-b)&127]*scale - t[i]; own 4 d's from smem+regs, boundary
    // neighbors via 2 shuffles.
    float dd0 = so2[w][(4 * l     - b) & 127] * scale - t4.x;
    float dd1 = so2[w][(4 * l + 1 - b) & 127] * scale - t4.y;
    float dd2 = so2[w][(4 * l + 2 - b) & 127] * scale - t4.z;
    float dd3 = so2[w][(4 * l + 3 - b) & 127] * scale - t4.w;
    float dm = __shfl_sync(0xffffffffu, dd3, (l + 31) & 31);  // d[4l-1] (circular)
    float dp = __shfl_sync(0xffffffffu, dd0, (l + 1) & 31);   // d[4l+4] (circular)
    float g0 = dd0 - 0.5f * (dm  + dd1);
    float g1 = dd1 - 0.5f * (dd0 + dd2);
    float g2 = dd2 - 0.5f * (dd1 + dd3);
    float g3 = dd3 - 0.5f * (dd2 + dp);
    float gg = fmaf(g0, g0, fmaf(g1, g1, fmaf(g2, g2, g3 * g3)));
#pragma unroll
    for (int s = 16; s > 0; s >>= 1) gg += __shfl_xor_sync(0xffffffffu, gg, s);

    // ---- per-block partial (fixed order: warp 0..3) ----
    if (l == 0) wres[w] = make_float4((float)b, fabsf(scale - 1.0f), sqrtf(gg), ms);
    __syncthreads();
    if (tid == 0) {
        float4 r = wres[0];
#pragma unroll
        for (int k = 1; k < RPB; k++) {
            float4 q = wres[k];
            r.x += q.x; r.y += q.y; r.z += q.z; r.w += q.w;
        }
        g_part[blockIdx.x] = r;
        __threadfence();
        unsigned int old = atomicAdd(&g_ticket, 1u);
        sLast = (old == NBLK - 1) ? 1u : 0u;
    }
    __syncthreads();

    // ---- last block finalizes (deterministic fixed-order reduction) ----
    if (sLast) {
        float a = 0.f, bb = 0.f, c = 0.f, dd = 0.f;
#pragma unroll
        for (int i = tid; i < NBLK; i += 128) {
            float4 q = g_part[i];
            a += q.x; bb += q.y; c += q.z; dd += q.w;
        }
        float4* fr = (float4*)&so2[0][0];   // reuse smem
        fr[tid] = make_float4(a, bb, c, dd);
        __syncthreads();
#pragma unroll
        for (int stp = 64; stp > 0; stp >>= 1) {
            if (tid < stp) {
                float4 x = fr[tid], y = fr[tid + stp];
                fr[tid] = make_float4(x.x + y.x, x.y + y.y, x.z + y.z, x.w + y.w);
            }
            __syncthreads();
        }
        if (tid == 0) {
            float4 r = fr[0];
            out[0] = 50.0f * r.x + 100.0f * r.y + 0.1f * r.z + sqrtf(r.w);
            g_ticket = 0u;   // reset for next graph replay
        }
    }
}

extern "C" void kernel_launch(void* const* d_in, const int* in_sizes, int n_in,
                              void* d_out, int out_size) {
    (void)n_in; (void)out_size; (void)in_sizes;
    const float* outp = (const float*)d_in[0];
    const float* trut = (const float*)d_in[1];
    float* res = (float*)d_out;
    loss3_fused<<<NBLK, 128>>>(outp, trut, res);
}

// round 8
// speedup vs baseline: 1.4574x; 1.4574x over previous
#include <cuda_runtime.h>
#include <cuda_bf16.h>

#define S 128
#define NROWS 4096
#define WPB 4                  // warps per block
#define RPB 8                  // rows per block (2 rows per warp)
#define NBLK (NROWS / RPB)     // 512 blocks

__device__ float4 g_part[NBLK];
__device__ unsigned int g_ticket;   // zero at load; reset by last block each run

__device__ __forceinline__ void fma2(unsigned long long& c,
                                     unsigned long long a,
                                     unsigned long long b) {
    asm("fma.rn.f32x2 %0, %1, %2, %0;" : "+l"(c) : "l"(a), "l"(b));
}
__device__ __forceinline__ float2 unpk(unsigned long long v) {
    float2 r;
    asm("mov.b64 {%0, %1}, %2;" : "=f"(r.x), "=f"(r.y) : "l"(v));
    return r;
}

__global__ void __launch_bounds__(128) loss3_fused(const float* __restrict__ outp,
                                                   const float* __restrict__ trut,
                                                   float* __restrict__ out) {
    __shared__ float so2[RPB][2 * S];   // output row, duplicated (wrap-free)
    __shared__ float so1[RPB][2 * S];   // so1[i] = o[(i+1) mod 128], duplicated
    __shared__ float st[RPB][S];        // truth row
    __shared__ float4 wres[RPB];
    __shared__ unsigned int sLast;

    const int tid = threadIdx.x;
    const int w = tid >> 5;       // warp: handles rows 2w (A) and 2w+1 (B)
    const int l = tid & 31;
    const int half = l >> 4;      // 0 -> row A, 1 -> row B (for the corr loop)
    const int p = l & 15;         // shift block: this lane owns shifts 8p..8p+7
    const int rA = 2 * w, rB = 2 * w + 1;
    const int rowA = blockIdx.x * RPB + rA;
    const int rowB = rowA + 1;

    // ---- load both rows (full warp each), build so2 / so1 / st ----
    float4 oA = *(const float4*)(outp + rowA * S + 4 * l);
    float4 tA = *(const float4*)(trut + rowA * S + 4 * l);
    float4 oB = *(const float4*)(outp + rowB * S + 4 * l);
    float4 tB = *(const float4*)(trut + rowB * S + 4 * l);
    *(float4*)&so2[rA][4 * l]     = oA;
    *(float4*)&so2[rA][S + 4 * l] = oA;
    *(float4*)&st[rA][4 * l]      = tA;
    *(float4*)&so2[rB][4 * l]     = oB;
    *(float4*)&so2[rB][S + 4 * l] = oB;
    *(float4*)&st[rB][4 * l]      = tB;
    float nxA = __shfl_sync(0xffffffffu, oA.x, (l + 1) & 31);
    float nxB = __shfl_sync(0xffffffffu, oB.x, (l + 1) & 31);
    float4 s1A = make_float4(oA.y, oA.z, oA.w, nxA);
    float4 s1B = make_float4(oB.y, oB.z, oB.w, nxB);
    *(float4*)&so1[rA][4 * l]     = s1A;
    *(float4*)&so1[rA][S + 4 * l] = s1A;
    *(float4*)&so1[rB][4 * l]     = s1B;
    *(float4*)&so1[rB][S + 4 * l] = s1B;
    __syncwarp();

    // ---- per-row MSE, max(o), max(t): 6 interleaved shuffle chains ----
    float dAx = oA.x - tA.x, dAy = oA.y - tA.y, dAz = oA.z - tA.z, dAw = oA.w - tA.w;
    float dBx = oB.x - tB.x, dBy = oB.y - tB.y, dBz = oB.z - tB.z, dBw = oB.w - tB.w;
    float msA = dAx * dAx + dAy * dAy + dAz * dAz + dAw * dAw;
    float msB = dBx * dBx + dBy * dBy + dBz * dBz + dBw * dBw;
    float moA = fmaxf(fmaxf(oA.x, oA.y), fmaxf(oA.z, oA.w));
    float moB = fmaxf(fmaxf(oB.x, oB.y), fmaxf(oB.z, oB.w));
    float mtA = fmaxf(fmaxf(tA.x, tA.y), fmaxf(tA.z, tA.w));
    float mtB = fmaxf(fmaxf(tB.x, tB.y), fmaxf(tB.z, tB.w));
#pragma unroll
    for (int s = 16; s > 0; s >>= 1) {
        msA += __shfl_xor_sync(0xffffffffu, msA, s);
        msB += __shfl_xor_sync(0xffffffffu, msB, s);
        moA = fmaxf(moA, __shfl_xor_sync(0xffffffffu, moA, s));
        moB = fmaxf(moB, __shfl_xor_sync(0xffffffffu, moB, s));
        mtA = fmaxf(mtA, __shfl_xor_sync(0xffffffffu, mtA, s));
        mtB = fmaxf(mtB, __shfl_xor_sync(0xffffffffu, mtB, s));
    }

    // ---- circular correlation: lane owns shifts s = 8p+k, k=0..7 ----
    // o[(j-s)&127] = so2[row][b0 + J + dj + 8 - k],  b0 = S - 8p - 8.
    // k even -> aligned pairs in so2; k odd -> aligned pairs in so1
    // (so1 index = so2 index - 1). Window quads slide by 4 floats per step.
    const int myrow = rA + half;
    const float* o2b = &so2[myrow][S - 8 * p - 8];
    const float* o1b = &so1[myrow][S - 8 * p - 8];
    const float* tb  = &st[myrow][0];

    unsigned long long A0 = 0, A1 = 0, A2 = 0, A3 = 0, A4 = 0, A5 = 0, A6 = 0, A7 = 0;
    unsigned long long Q1, Q2, Q3, R0, R1, R2, R3;
    Q1 = *(const unsigned long long*)(o2b + 2);          // so2 off (2,3)
    { ulonglong2 v = *(const ulonglong2*)(o2b + 4); Q2 = v.x; Q3 = v.y; }
    { ulonglong2 v = *(const ulonglong2*)(o1b);     R0 = v.x; R1 = v.y; }
    { ulonglong2 v = *(const ulonglong2*)(o1b + 4); R2 = v.x; R3 = v.y; }
#pragma unroll
    for (int J = 0; J < S; J += 4) {
        ulonglong2 q = *(const ulonglong2*)(o2b + J + 8);  // so2 off (8,9),(10,11)
        ulonglong2 r = *(const ulonglong2*)(o1b + J + 8);  // so1 off (8,9),(10,11)
        ulonglong2 t = *(const ulonglong2*)(tb + J);       // t (J,J+1),(J+2,J+3)
        fma2(A0, q.x, t.x);   // k=0: off(8,9)
        fma2(A1, R3,  t.x);   // k=1: so1 off(6,7)
        fma2(A2, Q3,  t.x);   // k=2: off(6,7)
        fma2(A3, R2,  t.x);   // k=3: so1 off(4,5)
        fma2(A4, Q2,  t.x);   // k=4: off(4,5)
        fma2(A5, R1,  t.x);   // k=5: so1 off(2,3)
        fma2(A6, Q1,  t.x);   // k=6: off(2,3)
        fma2(A7, R0,  t.x);   // k=7: so1 off(0,1)
        fma2(A0, q.y, t.y);   // k=0: off(10,11)
        fma2(A1, r.x, t.y);   // k=1: so1 off(8,9)
        fma2(A2, q.x, t.y);   // k=2: off(8,9)
        fma2(A3, R3,  t.y);   // k=3: so1 off(6,7)
        fma2(A4, Q3,  t.y);   // k=4: off(6,7)
        fma2(A5, R2,  t.y);   // k=5: so1 off(4,5)
        fma2(A6, Q2,  t.y);   // k=6: off(4,5)
        fma2(A7, R1,  t.y);   // k=7: so1 off(2,3)
        Q1 = Q3; Q2 = q.x; Q3 = q.y;
        R0 = R2; R1 = R3; R2 = r.x; R3 = r.y;
    }

    // ---- fold accumulators; argmax corr (tie -> smaller shift) ----
    float2 c0 = unpk(A0), c1 = unpk(A1), c2 = unpk(A2), c3 = unpk(A3);
    float2 c4 = unpk(A4), c5 = unpk(A5), c6 = unpk(A6), c7 = unpk(A7);
    float v0 = c0.x + c0.y, v1 = c1.x + c1.y, v2 = c2.x + c2.y, v3 = c3.x + c3.y;
    float v4 = c4.x + c4.y, v5 = c5.x + c5.y, v6 = c6.x + c6.y, v7 = c7.x + c7.y;
    float bc = v0; int bs = 8 * p;
    if (v1 > bc) { bc = v1; bs = 8 * p + 1; }
    if (v2 > bc) { bc = v2; bs = 8 * p + 2; }
    if (v3 > bc) { bc = v3; bs = 8 * p + 3; }
    if (v4 > bc) { bc = v4; bs = 8 * p + 4; }
    if (v5 > bc) { bc = v5; bs = 8 * p + 5; }
    if (v6 > bc) { bc = v6; bs = 8 * p + 6; }
    if (v7 > bc) { bc = v7; bs = 8 * p + 7; }
#pragma unroll
    for (int s = 8; s > 0; s >>= 1) {    // width-16: halves reduce independently
        float oc = __shfl_xor_sync(0xffffffffu, bc, s);
        int   os = __shfl_xor_sync(0xffffffffu, bs, s);
        if (oc > bc || (oc == bc && os < bs)) { bc = oc; bs = os; }
    }
    const int bA = __shfl_sync(0xffffffffu, bs, 0);
    const int bB = __shfl_sync(0xffffffffu, bs, 16);
    const float scaleA = mtA / moA;   // max(rolled)==max(output): roll is a permutation
    const float scaleB = mtB / moB;

    // ---- detail loss: g = cgrad(rolled*scale - truth); full warp per row ----
    float a0 = so2[rA][(4 * l     - bA) & 127] * scaleA - tA.x;
    float a1 = so2[rA][(4 * l + 1 - bA) & 127] * scaleA - tA.y;
    float a2 = so2[rA][(4 * l + 2 - bA) & 127] * scaleA - tA.z;
    float a3 = so2[rA][(4 * l + 3 - bA) & 127] * scaleA - tA.w;
    float b0 = so2[rB][(4 * l     - bB) & 127] * scaleB - tB.x;
    float b1 = so2[rB][(4 * l + 1 - bB) & 127] * scaleB - tB.y;
    float b2 = so2[rB][(4 * l + 2 - bB) & 127] * scaleB - tB.z;
    float b3 = so2[rB][(4 * l + 3 - bB) & 127] * scaleB - tB.w;
    float amL = __shfl_sync(0xffffffffu, a3, (l + 31) & 31);
    float apR = __shfl_sync(0xffffffffu, a0, (l + 1) & 31);
    float bmL = __shfl_sync(0xffffffffu, b3, (l + 31) & 31);
    float bpR = __shfl_sync(0xffffffffu, b0, (l + 1) & 31);
    float gA0 = a0 - 0.5f * (amL + a1);
    float gA1 = a1 - 0.5f * (a0 + a2);
    float gA2 = a2 - 0.5f * (a1 + a3);
    float gA3 = a3 - 0.5f * (a2 + apR);
    float gB0 = b0 - 0.5f * (bmL + b1);
    float gB1 = b1 - 0.5f * (b0 + b2);
    float gB2 = b2 - 0.5f * (b1 + b3);
    float gB3 = b3 - 0.5f * (b2 + bpR);
    float ggA = fmaf(gA0, gA0, fmaf(gA1, gA1, fmaf(gA2, gA2, gA3 * gA3)));
    float ggB = fmaf(gB0, gB0, fmaf(gB1, gB1, fmaf(gB2, gB2, gB3 * gB3)));
#pragma unroll
    for (int s = 16; s > 0; s >>= 1) {
        ggA += __shfl_xor_sync(0xffffffffu, ggA, s);
        ggB += __shfl_xor_sync(0xffffffffu, ggB, s);
    }

    // ---- per-block partial (fixed order over 8 rows) ----
    if (l == 0)  wres[rA] = make_float4((float)bA, fabsf(scaleA - 1.0f), sqrtf(ggA), msA);
    if (l == 16) wres[rB] = make_float4((float)bB, fabsf(scaleB - 1.0f), sqrtf(ggB), msB);
    __syncthreads();
    if (tid == 0) {
        float4 rsum = wres[0];
#pragma unroll
        for (int k = 1; k < RPB; k++) {
            float4 qq = wres[k];
            rsum.x += qq.x; rsum.y += qq.y; rsum.z += qq.z; rsum.w += qq.w;
        }
        g_part[blockIdx.x] = rsum;
        __threadfence();
        unsigned int old = atomicAdd(&g_ticket, 1u);
        sLast = (old == NBLK - 1) ? 1u : 0u;
    }
    __syncthreads();

    // ---- last block finalizes (deterministic fixed-order reduction) ----
    if (sLast) {
        float fa = 0.f, fb = 0.f, fc = 0.f, fd = 0.f;
#pragma unroll
        for (int i = tid; i < NBLK; i += 128) {
            float4 qq = g_part[i];
            fa += qq.x; fb += qq.y; fc += qq.z; fd += qq.w;
        }
        float4* fr = (float4*)&so2[0][0];   // reuse smem
        fr[tid] = make_float4(fa, fb, fc, fd);
        __syncthreads();
#pragma unroll
        for (int stp = 64; stp > 0; stp >>= 1) {
            if (tid < stp) {
                float4 x = fr[tid], y = fr[tid + stp];
                fr[tid] = make_float4(x.x + y.x, x.y + y.y, x.z + y.z, x.w + y.w);
            }
            __syncthreads();
        }
        if (tid == 0) {
            float4 rr = fr[0];
            out[0] = 50.0f * rr.x + 100.0f * rr.y + 0.1f * rr.z + sqrtf(rr.w);
            g_ticket = 0u;   // reset for next graph replay
        }
    }
}

extern "C" void kernel_launch(void* const* d_in, const int* in_sizes, int n_in,
                              void* d_out, int out_size) {
    (void)n_in; (void)out_size; (void)in_sizes;
    const float* outp = (const float*)d_in[0];
    const float* trut = (const float*)d_in[1];
    float* res = (float*)d_out;
    loss3_fused<<<NBLK, 128>>>(outp, trut, res);
}

// round 9
// speedup vs baseline: 1.4681x; 1.0074x over previous
#include <cuda_runtime.h>
#include <cuda_bf16.h>

#define S 128
#define NROWS 4096
#define RPB 4                 // rows per block (one warp per row)
#define NBLK (NROWS / RPB)    // 1024 blocks

__device__ float4 g_part[NBLK];
__device__ unsigned int g_ticket;   // zero at load; reset by last block each run

__device__ __forceinline__ void fma2(unsigned long long& c,
                                     unsigned long long a,
                                     unsigned long long b) {
    asm("fma.rn.f32x2 %0, %1, %2, %0;" : "+l"(c) : "l"(a), "l"(b));
}
__device__ __forceinline__ float2 unpk(unsigned long long v) {
    float2 r;
    asm("mov.b64 {%0, %1}, %2;" : "=f"(r.x), "=f"(r.y) : "l"(v));
    return r;
}

__global__ void __launch_bounds__(128) loss3_fused(const float* __restrict__ outp,
                                                   const float* __restrict__ trut,
                                                   float* __restrict__ out) {
    __shared__ float so2[RPB][2 * S];   // output row, duplicated (wrap-free)
    __shared__ float so1[RPB][2 * S];   // so1[i] = o[(i+1) mod 128], duplicated
    __shared__ float st[RPB][S];        // truth row
    __shared__ float4 wres[RPB];
    __shared__ unsigned int sLast;

    const int tid = threadIdx.x;
    const int w = tid >> 5;     // warp = row within block
    const int l = tid & 31;     // lane
    const int row = blockIdx.x * RPB + w;

    // ---- load row (coalesced float4), mirror into smem ----
    float4 o4 = *(const float4*)(outp + row * S + 4 * l);
    float4 t4 = *(const float4*)(trut + row * S + 4 * l);
    *(float4*)&so2[w][4 * l]     = o4;
    *(float4*)&so2[w][S + 4 * l] = o4;
    *(float4*)&st[w][4 * l]      = t4;
    // shifted copy: so1[4l..4l+3] = o[4l+1..4l+4]
    float nx = __shfl_sync(0xffffffffu, o4.x, (l + 1) & 31);
    float4 s1 = make_float4(o4.y, o4.z, o4.w, nx);
    *(float4*)&so1[w][4 * l]     = s1;
    *(float4*)&so1[w][S + 4 * l] = s1;
    __syncwarp();

    // ---- row MSE (direct), max(output), max(truth): warp shuffles ----
    float d0 = o4.x - t4.x, d1 = o4.y - t4.y, d2 = o4.z - t4.z, d3 = o4.w - t4.w;
    float ms = d0 * d0 + d1 * d1 + d2 * d2 + d3 * d3;
    float mo = fmaxf(fmaxf(o4.x, o4.y), fmaxf(o4.z, o4.w));
    float mt = fmaxf(fmaxf(t4.x, t4.y), fmaxf(t4.z, t4.w));
#pragma unroll
    for (int s = 16; s > 0; s >>= 1) {
        ms += __shfl_xor_sync(0xffffffffu, ms, s);
        mo = fmaxf(mo, __shfl_xor_sync(0xffffffffu, mo, s));
        mt = fmaxf(mt, __shfl_xor_sync(0xffffffffu, mt, s));
    }

    // ---- circular correlation, fully packed f32x2, scalar u64 carries ----
    // acc[k] = sum_j o[(j-(4l+k))&127] * t[j];  o[(j-s)&127] = so2[j-s+S]
    // ob[i] = so2[(S-4l-4)+i], ob1[i] = so1[(S-4l-4)+i] = o at ob-offset i+1.
    // Per J step (operands are aligned u64 halves of LDS.128 results):
    //   k=0: (J+4,J+5)t01 (J+6,J+7)t23  = U.x,  U.y
    //   k=1: (J+3,J+4)t01 (J+5,J+6)t23  = pVy,  V.x     (so1: off-1)
    //   k=2: (J+2,J+3)t01 (J+4,J+5)t23  = pUy,  U.x
    //   k=3: (J+1,J+2)t01 (J+3,J+4)t23  = pVx,  pVy
    const float* ob  = &so2[w][S - 4 * l - 4];
    const float* ob1 = &so1[w][S - 4 * l - 4];
    const float* tb  = &st[w][0];
    unsigned long long A0 = 0ull, A1 = 0ull, A2 = 0ull, A3 = 0ull;
    unsigned long long pUy = *(const unsigned long long*)(ob + 2);
    unsigned long long pVx, pVy;
    { ulonglong2 v = *(const ulonglong2*)(ob1); pVx = v.x; pVy = v.y; }
#pragma unroll
    for (int J = 0; J < S; J += 4) {
        ulonglong2 U = *(const ulonglong2*)(ob + J + 4);
        ulonglong2 V = *(const ulonglong2*)(ob1 + J + 4);
        ulonglong2 T = *(const ulonglong2*)(tb + J);   // uniform -> broadcast
        fma2(A0, U.x, T.x);
        fma2(A1, pVy, T.x);
        fma2(A2, pUy, T.x);
        fma2(A3, pVx, T.x);
        fma2(A0, U.y, T.y);
        fma2(A1, V.x, T.y);
        fma2(A2, U.x, T.y);
        fma2(A3, pVy, T.y);
        pUy = U.y;
        pVx = V.x;
        pVy = V.y;
    }
    float2 p0 = unpk(A0), p1 = unpk(A1), p2 = unpk(A2), p3 = unpk(A3);
    float acc0 = p0.x + p0.y;
    float acc1 = p1.x + p1.y;
    float acc2 = p2.x + p2.y;
    float acc3 = p3.x + p3.y;

    // ---- argmax corr == argmin shiftDiff; tie-break -> smaller shift ----
    float bc = acc0; int bs = 4 * l;
    if (acc1 > bc) { bc = acc1; bs = 4 * l + 1; }
    if (acc2 > bc) { bc = acc2; bs = 4 * l + 2; }
    if (acc3 > bc) { bc = acc3; bs = 4 * l + 3; }
#pragma unroll
    for (int s = 16; s > 0; s >>= 1) {
        float oc = __shfl_xor_sync(0xffffffffu, bc, s);
        int   os = __shfl_xor_sync(0xffffffffu, bs, s);
        if (oc > bc || (oc == bc && os < bs)) { bc = oc; bs = os; }
    }
    const int b = bs;
    const float scale = mt / mo;   // max(rolled) == max(output): roll is a permutation

    // ---- detail loss: g = cgrad(rolled*scale - truth), cgrad linear ----
    float dd0 = so2[w][(4 * l     - b) & 127] * scale - t4.x;
    float dd1 = so2[w][(4 * l + 1 - b) & 127] * scale - t4.y;
    float dd2 = so2[w][(4 * l + 2 - b) & 127] * scale - t4.z;
    float dd3 = so2[w][(4 * l + 3 - b) & 127] * scale - t4.w;
    float dm = __shfl_sync(0xffffffffu, dd3, (l + 31) & 31);  // d[4l-1] (circular)
    float dp = __shfl_sync(0xffffffffu, dd0, (l + 1) & 31);   // d[4l+4] (circular)
    float g0 = dd0 - 0.5f * (dm  + dd1);
    float g1 = dd1 - 0.5f * (dd0 + dd2);
    float g2 = dd2 - 0.5f * (dd1 + dd3);
    float g3 = dd3 - 0.5f * (dd2 + dp);
    float gg = fmaf(g0, g0, fmaf(g1, g1, fmaf(g2, g2, g3 * g3)));
#pragma unroll
    for (int s = 16; s > 0; s >>= 1) gg += __shfl_xor_sync(0xffffffffu, gg, s);

    // ---- per-block partial (fixed order: warp 0..3) ----
    if (l == 0) wres[w] = make_float4((float)b, fabsf(scale - 1.0f), sqrtf(gg), ms);
    __syncthreads();
    if (tid == 0) {
        float4 r = wres[0];
#pragma unroll
        for (int k = 1; k < RPB; k++) {
            float4 q = wres[k];
            r.x += q.x; r.y += q.y; r.z += q.z; r.w += q.w;
        }
        g_part[blockIdx.x] = r;
        __threadfence();
        unsigned int old = atomicAdd(&g_ticket, 1u);
        sLast = (old == NBLK - 1) ? 1u : 0u;
    }
    __syncthreads();

    // ---- last block finalizes (deterministic fixed-order reduction) ----
    if (sLast) {
        float a = 0.f, bb = 0.f, c = 0.f, dd = 0.f;
#pragma unroll
        for (int i = tid; i < NBLK; i += 128) {
            float4 q = g_part[i];
            a += q.x; bb += q.y; c += q.z; dd += q.w;
        }
        float4* fr = (float4*)&so2[0][0];   // reuse smem
        fr[tid] = make_float4(a, bb, c, dd);
        __syncthreads();
#pragma unroll
        for (int stp = 64; stp > 0; stp >>= 1) {
            if (tid < stp) {
                float4 x = fr[tid], y = fr[tid + stp];
                fr[tid] = make_float4(x.x + y.x, x.y + y.y, x.z + y.z, x.w + y.w);
            }
            __syncthreads();
        }
        if (tid == 0) {
            float4 r = fr[0];
            out[0] = 50.0f * r.x + 100.0f * r.y + 0.1f * r.z + sqrtf(r.w);
            g_ticket = 0u;   // reset for next graph replay
        }
    }
}

extern "C" void kernel_launch(void* const* d_in, const int* in_sizes, int n_in,
                              void* d_out, int out_size) {
    (void)n_in; (void)out_size; (void)in_sizes;
    const float* outp = (const float*)d_in[0];
    const float* trut = (const float*)d_in[1];
    float* res = (float*)d_out;
    loss3_fused<<<NBLK, 128>>>(outp, trut, res);
}

// round 10
// speedup vs baseline: 1.7881x; 1.2179x over previous
#include <cuda_runtime.h>
#include <cuda_bf16.h>

#define S 128
#define NROWS 4096
#define RPB 4                 // rows per block (one warp per row)
#define NBLK (NROWS / RPB)    // 1024 blocks

// padded index map: insert 4 pad floats after every 8 (lane stride 48B -> no bank conflicts)
#define PADIDX(m) ((m) + 4 * ((m) >> 3))
#define PADLEN 384            // covers orig [0,256): PADIDX(252)+4 = 380 -> 384

__device__ float4 g_part[NBLK];
__device__ unsigned int g_ticket;   // zero at load; reset by last block each run

__device__ __forceinline__ void fma2(unsigned long long& c,
                                     unsigned long long a,
                                     unsigned long long b) {
    asm("fma.rn.f32x2 %0, %1, %2, %0;" : "+l"(c) : "l"(a), "l"(b));
}
__device__ __forceinline__ void add2(unsigned long long& c, unsigned long long a) {
    asm("add.rn.f32x2 %0, %0, %1;" : "+l"(c) : "l"(a));
}
__device__ __forceinline__ float2 unpk(unsigned long long v) {
    float2 r;
    asm("mov.b64 {%0, %1}, %2;" : "=f"(r.x), "=f"(r.y) : "l"(v));
    return r;
}

__global__ void __launch_bounds__(128) loss3_fused(const float* __restrict__ outp,
                                                   const float* __restrict__ trut,
                                                   float* __restrict__ out) {
    __shared__ float soP[RPB][PADLEN];   // padded o, duplicated (wrap-free)
    __shared__ float so1P[RPB][PADLEN];  // padded o[(i+1) mod 128], duplicated
    __shared__ float stT[RPB][S];        // truth row (plain)
    __shared__ float sod[RPB][S];        // plain o row (for detail phase)
    __shared__ float4 wres[RPB];
    __shared__ unsigned int sLast;

    const int tid = threadIdx.x;
    const int w = tid >> 5;       // warp = row within block
    const int l = tid & 31;       // lane
    const int h = l >> 4;         // j-half: 0 -> j[0,64), 1 -> j[64,128)
    const int p = l & 15;         // lane owns shifts 8p..8p+7
    const int row = blockIdx.x * RPB + w;

    // ---- load row (coalesced float4), build padded smem images ----
    float4 o4 = *(const float4*)(outp + row * S + 4 * l);
    float4 t4 = *(const float4*)(trut + row * S + 4 * l);
    const int ps = PADIDX(4 * l);
    *(float4*)&soP[w][ps]        = o4;
    *(float4*)&soP[w][ps + 192]  = o4;            // orig +128 -> padded +192
    *(float4*)&stT[w][4 * l]     = t4;
    *(float4*)&sod[w][4 * l]     = o4;
    float nx = __shfl_sync(0xffffffffu, o4.x, (l + 1) & 31);
    float4 s1 = make_float4(o4.y, o4.z, o4.w, nx);  // o[4l+1..4l+4]
    *(float4*)&so1P[w][ps]       = s1;
    *(float4*)&so1P[w][ps + 192] = s1;
    __syncwarp();

    // ---- row MSE, max(output), max(truth): warp shuffles ----
    float d0 = o4.x - t4.x, d1 = o4.y - t4.y, d2 = o4.z - t4.z, d3 = o4.w - t4.w;
    float ms = d0 * d0 + d1 * d1 + d2 * d2 + d3 * d3;
    float mo = fmaxf(fmaxf(o4.x, o4.y), fmaxf(o4.z, o4.w));
    float mt = fmaxf(fmaxf(t4.x, t4.y), fmaxf(t4.z, t4.w));
#pragma unroll
    for (int s = 16; s > 0; s >>= 1) {
        ms += __shfl_xor_sync(0xffffffffu, ms, s);
        mo = fmaxf(mo, __shfl_xor_sync(0xffffffffu, mo, s));
        mt = fmaxf(mt, __shfl_xor_sync(0xffffffffu, mt, s));
    }

    // ---- circular correlation: shifts s = 8p+k (k=0..7), j-half per lane ----
    // o[(j-s)&127] = orig so2[b0 + j + (8-k)], b0 = 128-8p-8 (multiple of 8).
    // Padded: lane base = PADIDX(b0) + PADIDX(64h) = 12*(15-p) + 96h; offsets
    // PADIDX(J+off) are compile-time. Even k from soP, odd k from so1P (off-1).
    const float* oP  = &soP[w][12 * (15 - p) + 96 * h];
    const float* oP1 = &so1P[w][12 * (15 - p) + 96 * h];
    const float* tb  = &stT[w][64 * h];

    unsigned long long A0 = 0, A1 = 0, A2 = 0, A3 = 0, A4 = 0, A5 = 0, A6 = 0, A7 = 0;
    unsigned long long Q1, Q2, Q3, R0, R1, R2, R3;
    Q1 = *(const unsigned long long*)(oP + PADIDX(2));           // orig (2,3)
    { ulonglong2 v = *(const ulonglong2*)(oP + PADIDX(4));  Q2 = v.x; Q3 = v.y; }
    { ulonglong2 v = *(const ulonglong2*)(oP1 + PADIDX(0)); R0 = v.x; R1 = v.y; }
    { ulonglong2 v = *(const ulonglong2*)(oP1 + PADIDX(4)); R2 = v.x; R3 = v.y; }
#pragma unroll
    for (int J = 0; J < 64; J += 4) {
        ulonglong2 q = *(const ulonglong2*)(oP + PADIDX(J + 8));   // orig (8,9),(10,11)
        ulonglong2 r = *(const ulonglong2*)(oP1 + PADIDX(J + 8));
        ulonglong2 t = *(const ulonglong2*)(tb + J);               // (J,J+1),(J+2,J+3)
        fma2(A0, q.x, t.x);   // k=0: off(8,9)
        fma2(A1, R3,  t.x);   // k=1: so1 off(6,7)
        fma2(A2, Q3,  t.x);   // k=2: off(6,7)
        fma2(A3, R2,  t.x);   // k=3: so1 off(4,5)
        fma2(A4, Q2,  t.x);   // k=4: off(4,5)
        fma2(A5, R1,  t.x);   // k=5: so1 off(2,3)
        fma2(A6, Q1,  t.x);   // k=6: off(2,3)
        fma2(A7, R0,  t.x);   // k=7: so1 off(0,1)
        fma2(A0, q.y, t.y);   // k=0: off(10,11)
        fma2(A1, r.x, t.y);   // k=1: so1 off(8,9)
        fma2(A2, q.x, t.y);   // k=2: off(8,9)
        fma2(A3, R3,  t.y);   // k=3: so1 off(6,7)
        fma2(A4, Q3,  t.y);   // k=4: off(6,7)
        fma2(A5, R2,  t.y);   // k=5: so1 off(4,5)
        fma2(A6, Q2,  t.y);   // k=6: off(4,5)
        fma2(A7, R1,  t.y);   // k=7: so1 off(2,3)
        Q1 = Q3; Q2 = q.x; Q3 = q.y;
        R0 = R2; R1 = R3; R2 = r.x; R3 = r.y;
    }

    // ---- combine j-halves (lanes l and l^16 hold same shifts) ----
    add2(A0, __shfl_xor_sync(0xffffffffu, A0, 16));
    add2(A1, __shfl_xor_sync(0xffffffffu, A1, 16));
    add2(A2, __shfl_xor_sync(0xffffffffu, A2, 16));
    add2(A3, __shfl_xor_sync(0xffffffffu, A3, 16));
    add2(A4, __shfl_xor_sync(0xffffffffu, A4, 16));
    add2(A5, __shfl_xor_sync(0xffffffffu, A5, 16));
    add2(A6, __shfl_xor_sync(0xffffffffu, A6, 16));
    add2(A7, __shfl_xor_sync(0xffffffffu, A7, 16));
    float2 c0 = unpk(A0), c1 = unpk(A1), c2 = unpk(A2), c3 = unpk(A3);
    float2 c4 = unpk(A4), c5 = unpk(A5), c6 = unpk(A6), c7 = unpk(A7);
    float v0 = c0.x + c0.y, v1 = c1.x + c1.y, v2 = c2.x + c2.y, v3 = c3.x + c3.y;
    float v4 = c4.x + c4.y, v5 = c5.x + c5.y, v6 = c6.x + c6.y, v7 = c7.x + c7.y;

    // ---- argmax corr == argmin shiftDiff; tie-break -> smaller shift ----
    float bc = v0; int bs = 8 * p;
    if (v1 > bc) { bc = v1; bs = 8 * p + 1; }
    if (v2 > bc) { bc = v2; bs = 8 * p + 2; }
    if (v3 > bc) { bc = v3; bs = 8 * p + 3; }
    if (v4 > bc) { bc = v4; bs = 8 * p + 4; }
    if (v5 > bc) { bc = v5; bs = 8 * p + 5; }
    if (v6 > bc) { bc = v6; bs = 8 * p + 6; }
    if (v7 > bc) { bc = v7; bs = 8 * p + 7; }
#pragma unroll
    for (int s = 8; s > 0; s >>= 1) {   // halves identical -> width-16 reduce
        float oc = __shfl_xor_sync(0xffffffffu, bc, s);
        int   os = __shfl_xor_sync(0xffffffffu, bs, s);
        if (oc > bc || (oc == bc && os < bs)) { bc = oc; bs = os; }
    }
    const int b = bs;                  // all lanes agree
    const float scale = mt / mo;       // max(rolled) == max(output)

    // ---- detail loss: g = cgrad(rolled*scale - truth), cgrad linear ----
    float dd0 = sod[w][(4 * l     - b) & 127] * scale - t4.x;
    float dd1 = sod[w][(4 * l + 1 - b) & 127] * scale - t4.y;
    float dd2 = sod[w][(4 * l + 2 - b) & 127] * scale - t4.z;
    float dd3 = sod[w][(4 * l + 3 - b) & 127] * scale - t4.w;
    float dm = __shfl_sync(0xffffffffu, dd3, (l + 31) & 31);  // d[4l-1] circular
    float dp = __shfl_sync(0xffffffffu, dd0, (l + 1) & 31);   // d[4l+4] circular
    float g0 = dd0 - 0.5f * (dm  + dd1);
    float g1 = dd1 - 0.5f * (dd0 + dd2);
    float g2 = dd2 - 0.5f * (dd1 + dd3);
    float g3 = dd3 - 0.5f * (dd2 + dp);
    float gg = fmaf(g0, g0, fmaf(g1, g1, fmaf(g2, g2, g3 * g3)));
#pragma unroll
    for (int s = 16; s > 0; s >>= 1) gg += __shfl_xor_sync(0xffffffffu, gg, s);

    // ---- per-block partial (fixed order: warp 0..3) ----
    if (l == 0) wres[w] = make_float4((float)b, fabsf(scale - 1.0f), sqrtf(gg), ms);
    __syncthreads();
    if (tid == 0) {
        float4 r = wres[0];
#pragma unroll
        for (int k = 1; k < RPB; k++) {
            float4 q = wres[k];
            r.x += q.x; r.y += q.y; r.z += q.z; r.w += q.w;
        }
        g_part[blockIdx.x] = r;
        __threadfence();
        unsigned int old = atomicAdd(&g_ticket, 1u);
        sLast = (old == NBLK - 1) ? 1u : 0u;
    }
    __syncthreads();

    // ---- last block finalizes (deterministic fixed-order reduction) ----
    if (sLast) {
        float a = 0.f, bb = 0.f, c = 0.f, dd = 0.f;
#pragma unroll
        for (int i = tid; i < NBLK; i += 128) {
            float4 q = g_part[i];
            a += q.x; bb += q.y; c += q.z; dd += q.w;
        }
        float4* fr = (float4*)&soP[0][0];   // reuse smem
        fr[tid] = make_float4(a, bb, c, dd);
        __syncthreads();
#pragma unroll
        for (int stp = 64; stp > 0; stp >>= 1) {
            if (tid < stp) {
                float4 x = fr[tid], y = fr[tid + stp];
                fr[tid] = make_float4(x.x + y.x, x.y + y.y, x.z + y.z, x.w + y.w);
            }
            __syncthreads();
        }
        if (tid == 0) {
            float4 r = fr[0];
            out[0] = 50.0f * r.x + 100.0f * r.y + 0.1f * r.z + sqrtf(r.w);
            g_ticket = 0u;   // reset for next graph replay
        }
    }
}

extern "C" void kernel_launch(void* const* d_in, const int* in_sizes, int n_in,
                              void* d_out, int out_size) {
    (void)n_in; (void)out_size; (void)in_sizes;
    const float* outp = (const float*)d_in[0];
    const float* trut = (const float*)d_in[1];
    float* res = (float*)d_out;
    loss3_fused<<<NBLK, 128>>>(outp, trut, res);
}